// round 7
// baseline (speedup 1.0000x reference)
#include <cuda_runtime.h>
#include <cstdint>

// Problem constants
#define NN 20000
#define KK 32
#define DD 128

#define FULLMASK 0xffffffffu
#define AS_STRIDE 132   // floats; 528B row, 16B aligned for cp.async

// Scratch
__device__ float  g_tsf[NN * DD];          // self_feats @ self_weights
__device__ float2 g_wpack[16 * 16 * 32];   // link_weights packed in mma-B-fragment order (tf32)

__device__ __forceinline__ uint32_t f2tf32(float x) {
    uint32_t r;
    asm("cvt.rna.tf32.f32 %0, %1;" : "=r"(r) : "f"(x));
    return r;
}

__device__ __forceinline__ float sigf(float x) {
    return __fdividef(1.0f, 1.0f + __expf(-x));
}

__device__ __forceinline__ void mma_tf32(float* c, const uint32_t* a, uint32_t b0, uint32_t b1) {
    asm volatile(
        "mma.sync.aligned.m16n8k8.row.col.f32.tf32.tf32.f32 "
        "{%0,%1,%2,%3}, {%4,%5,%6,%7}, {%8,%9}, {%0,%1,%2,%3};\n"
        : "+f"(c[0]), "+f"(c[1]), "+f"(c[2]), "+f"(c[3])
        : "r"(a[0]), "r"(a[1]), "r"(a[2]), "r"(a[3]), "r"(b0), "r"(b1));
}

__device__ __forceinline__ void cp_async16(float* smem_dst, const float* gsrc) {
    uint32_t s = (uint32_t)__cvta_generic_to_shared(smem_dst);
    asm volatile("cp.async.cg.shared.global [%0], [%1], 16;\n" :: "r"(s), "l"(gsrc));
}

// ---------------------------------------------------------------------------
// Setup 1: pack link_weights into per-fragment lane order (tf32).
// Fragment (ks, ct): lane (g = l>>2, tg = l&3) holds
//   b0 = W[ks*8 + tg    ][ct*8 + g]
//   b1 = W[ks*8 + 4 + tg][ct*8 + g]
// ---------------------------------------------------------------------------
__global__ __launch_bounds__(256) void pack_w_kernel(const float* __restrict__ lW)
{
    int i = blockIdx.x * 256 + threadIdx.x;     // 0 .. 8191
    int ks = i >> 9;
    int rem = i & 511;
    int ct = rem >> 5;
    int lane = rem & 31;
    int g = lane >> 2, tg = lane & 3;
    float2 v;
    v.x = __uint_as_float(f2tf32(lW[(ks * 8 + tg) * 128 + ct * 8 + g]));
    v.y = __uint_as_float(f2tf32(lW[(ks * 8 + 4 + tg) * 128 + ct * 8 + g]));
    g_wpack[i] = v;
}

// ---------------------------------------------------------------------------
// Setup 2: g_tsf = self_feats @ self_weights. 32 nodes/CTA, 256 thr, fp32.
// ---------------------------------------------------------------------------
#define PRO_BS 132
#define PRO_AS 36

__global__ __launch_bounds__(256) void tsf_gemm_kernel(
    const float* __restrict__ sf, const float* __restrict__ W)
{
    extern __shared__ float sm[];
    float* sB = sm;                  // [128][132]
    float* sA = sm + 128 * PRO_BS;   // [128][36]

    int tid = threadIdx.x;
    int nb = blockIdx.x * 32;

    for (int i = tid; i < 4096; i += 256) {
        int d = i >> 5, c = (i & 31) * 4;
        float4 v = *(const float4*)(W + d * 128 + c);
        *(float4*)(sB + d * PRO_BS + c) = v;
    }
    for (int i = tid; i < 4096; i += 256) {
        int m = i >> 7, d = i & 127;
        sA[d * PRO_AS + m] = sf[(nb + m) * 128 + d];
    }
    __syncthreads();

    int tr = tid >> 5, lane = tid & 31;
    int m0 = tr * 4, e0 = lane * 4;
    float acc[4][4] = {};

#pragma unroll 4
    for (int d = 0; d < 128; ++d) {
        float4 b = *(float4*)(sB + d * PRO_BS + e0);
        float4 a = *(float4*)(sA + d * PRO_AS + m0);
        float av[4] = {a.x, a.y, a.z, a.w};
        float bv[4] = {b.x, b.y, b.z, b.w};
#pragma unroll
        for (int i = 0; i < 4; ++i)
#pragma unroll
            for (int j = 0; j < 4; ++j)
                acc[i][j] += av[i] * bv[j];
    }
#pragma unroll
    for (int i = 0; i < 4; ++i) {
        float4 o = make_float4(acc[i][0], acc[i][1], acc[i][2], acc[i][3]);
        *(float4*)(g_tsf + (size_t)(nb + m0 + i) * 128 + e0) = o;
    }
}

// ---------------------------------------------------------------------------
// Main fused kernel. 4 nodes (128 rows) per CTA, 256 threads, 2 CTAs/SM.
//  - A (link tile) via cp.async -> smem (raw fp32, tf32-truncated by mma)
//  - B from g_wpack: 1 coalesced LDG.64 per fragment (L2-hot)
//  - gate: coalesced LDG.128 row reads + warp reduce
//  - GEMM: warp = 64 rows x 32 cols, m16n8k8 tf32
//  - P = sigmoid(acc)*gate/(32p) stored into dead A-tile smem
//  - reduce phase: coalesced neigh + P, * g_tsf, relu, store
// ---------------------------------------------------------------------------
__global__ __launch_bounds__(256, 2) void rwagg_fused_kernel(
    const float* __restrict__ self_vecs, const float* __restrict__ neigh,
    const float* __restrict__ link, const float* __restrict__ probs,
    const float* __restrict__ gsw, const float* __restrict__ gnw,
    const float* __restrict__ glw, float* __restrict__ out)
{
    extern __shared__ float sm[];
    float* As       = sm;                       // [128][132] link tile -> later P
    float* s_gnw    = As + 128 * AS_STRIDE;     // 128
    float* s_glw    = s_gnw + 128;              // 128
    float* s_gscale = s_glw + 128;              // 128
    float* s_tself  = s_gscale + 128;           // 4
    float* s_outb   = s_tself + 4;              // 512

    int tid = threadIdx.x, lane = tid & 31, wid = tid >> 5;
    int g = lane >> 2, tg = lane & 3;
    int node4 = blockIdx.x * 4;
    int row_base = blockIdx.x * 128;

    // ---- stage 0: cp.async the A (link) tile -----------------------------
    for (int i = tid; i < 4096; i += 256) {
        int r = i >> 5, c = (i & 31) * 4;
        cp_async16(As + r * AS_STRIDE + c,
                   link + (size_t)(row_base + r) * 128 + c);
    }
    asm volatile("cp.async.commit_group;\n");

    // in the shadow: gate weight vectors + tself dots
    if (tid < 128) s_gnw[tid] = __ldg(gnw + tid);
    else           s_glw[tid - 128] = __ldg(glw + tid - 128);

    if (wid < 4) {
        float4 sv = __ldg((const float4*)(self_vecs + (size_t)(node4 + wid) * 128 + lane * 4));
        float4 gw = __ldg((const float4*)(gsw + lane * 4));
        float p = sv.x * gw.x + sv.y * gw.y + sv.z * gw.z + sv.w * gw.w;
#pragma unroll
        for (int off = 16; off; off >>= 1) p += __shfl_xor_sync(FULLMASK, p, off);
        if (lane == 0) s_tself[wid] = p;
    }

    asm volatile("cp.async.wait_group 0;\n" ::: "memory");
    __syncthreads();

    // ---- gate: warp w handles rows w*16 .. w*16+15, fully coalesced ------
    {
        int rb = wid * 16;
#pragma unroll
        for (int j = 0; j < 16; ++j) {
            int m = rb + j;
            float4 n4 = __ldg((const float4*)(neigh + (size_t)(row_base + m) * 128 + lane * 4));
            float4 l4 = *(const float4*)(As + m * AS_STRIDE + lane * 4);
            float4 gw = *(const float4*)(s_gnw + lane * 4);
            float4 lw = *(const float4*)(s_glw + lane * 4);
            float dot = n4.x * gw.x + n4.y * gw.y + n4.z * gw.z + n4.w * gw.w
                      + l4.x * lw.x + l4.y * lw.y + l4.z * lw.z + l4.w * lw.w;
#pragma unroll
            for (int off = 16; off; off >>= 1) dot += __shfl_xor_sync(FULLMASK, dot, off);
            if (lane == 0) {
                float logit = s_tself[m >> 5] + dot;
                s_gscale[m] = sigf(logit) * __fdividef(1.0f, 32.0f * __ldg(probs + row_base + m));
            }
        }
    }
    __syncthreads();

    // ---- GEMM: warp (wr, wc) -> rows wr*64..+63, cols wc*32..+31 ---------
    int wr = wid & 1, wc = wid >> 1;
    float acc[4][4][4];
#pragma unroll
    for (int mt = 0; mt < 4; ++mt)
#pragma unroll
        for (int nt = 0; nt < 4; ++nt)
#pragma unroll
            for (int q = 0; q < 4; ++q) acc[mt][nt][q] = 0.0f;

    const float2* wp = g_wpack + (size_t)(wc * 4) * 32 + lane;
#pragma unroll
    for (int ks = 0; ks < 16; ++ks) {
        int k0 = ks * 8;
        float2 bf[4];
#pragma unroll
        for (int nt = 0; nt < 4; ++nt)
            bf[nt] = __ldg(wp + ks * 512 + nt * 32);
#pragma unroll
        for (int mt = 0; mt < 4; ++mt) {
            const float* ap = As + (wr * 64 + mt * 16) * AS_STRIDE + k0;
            uint32_t a[4];
            a[0] = __float_as_uint(ap[g * AS_STRIDE + tg]);
            a[1] = __float_as_uint(ap[(8 + g) * AS_STRIDE + tg]);
            a[2] = __float_as_uint(ap[g * AS_STRIDE + 4 + tg]);
            a[3] = __float_as_uint(ap[(8 + g) * AS_STRIDE + 4 + tg]);
#pragma unroll
            for (int nt = 0; nt < 4; ++nt)
                mma_tf32(acc[mt][nt], a,
                         __float_as_uint(bf[nt].x), __float_as_uint(bf[nt].y));
        }
    }

    // all warps done reading A fragments before P overwrites the tile
    __syncthreads();

    // ---- P = sigmoid(acc) * gscale -> reuse As ---------------------------
#pragma unroll
    for (int mt = 0; mt < 4; ++mt) {
        int r1 = wr * 64 + mt * 16 + g;
        int r2 = r1 + 8;
        float gs1 = s_gscale[r1];
        float gs2 = s_gscale[r2];
#pragma unroll
        for (int nt = 0; nt < 4; ++nt) {
            int c = wc * 32 + nt * 8 + tg * 2;
            float2 p1, p2;
            p1.x = sigf(acc[mt][nt][0]) * gs1;
            p1.y = sigf(acc[mt][nt][1]) * gs1;
            p2.x = sigf(acc[mt][nt][2]) * gs2;
            p2.y = sigf(acc[mt][nt][3]) * gs2;
            *(float2*)(As + r1 * AS_STRIDE + c) = p1;
            *(float2*)(As + r2 * AS_STRIDE + c) = p2;
        }
    }
    __syncthreads();

    // ---- reduce: coalesced neigh * P, sum over k -------------------------
    {
        int e = tid & 127, h = tid >> 7;
        float accn[4];
#pragma unroll
        for (int n = 0; n < 4; ++n) {
            float s = 0.0f;
            int m0 = n * 32 + h * 16;
#pragma unroll
            for (int k = 0; k < 16; ++k) {
                int m = m0 + k;
                s = fmaf(__ldg(neigh + (size_t)(row_base + m) * 128 + e),
                         As[m * AS_STRIDE + e], s);
            }
            accn[n] = s;
        }
        if (h == 1) {
#pragma unroll
            for (int n = 0; n < 4; ++n) s_outb[n * 128 + e] = accn[n];
        }
        __syncthreads();
        if (h == 0) {
#pragma unroll
            for (int n = 0; n < 4; ++n) {
                float v = (accn[n] + s_outb[n * 128 + e])
                        * g_tsf[(size_t)(node4 + n) * 128 + e];
                out[(size_t)(node4 + n) * 128 + e] = fmaxf(v, 0.0f);
            }
        }
    }
}

// ---------------------------------------------------------------------------
extern "C" void kernel_launch(void* const* d_in, const int* in_sizes, int n_in,
                              void* d_out, int out_size)
{
    const float* self_feats = (const float*)d_in[0];
    const float* self_vecs  = (const float*)d_in[1];
    const float* neigh      = (const float*)d_in[2];
    const float* link       = (const float*)d_in[3];
    const float* probs      = (const float*)d_in[4];
    const float* gsw        = (const float*)d_in[5];
    const float* gnw        = (const float*)d_in[6];
    const float* glw        = (const float*)d_in[7];
    const float* sW         = (const float*)d_in[8];
    const float* lW         = (const float*)d_in[9];
    float* out = (float*)d_out;

    const int pro_smem  = (128 * PRO_BS + 128 * PRO_AS) * 4;                 // 86016 B
    const int main_smem = (128 * AS_STRIDE + 3 * 128 + 4 + 512) * 4;         // 71184 B

    cudaFuncSetAttribute(tsf_gemm_kernel,
                         cudaFuncAttributeMaxDynamicSharedMemorySize, pro_smem);
    cudaFuncSetAttribute(rwagg_fused_kernel,
                         cudaFuncAttributeMaxDynamicSharedMemorySize, main_smem);

    pack_w_kernel<<<32, 256>>>(lW);
    tsf_gemm_kernel<<<NN / 32, 256, pro_smem>>>(self_feats, sW);
    rwagg_fused_kernel<<<NN / 4, 256, main_smem>>>(
        self_vecs, neigh, link, probs, gsw, gnw, glw, out);
}

// round 8
// speedup vs baseline: 1.6445x; 1.6445x over previous
#include <cuda_runtime.h>
#include <cstdint>

// Problem constants
#define NN 20000
#define KK 32
#define DD 128

#define FULLMASK 0xffffffffu
#define AS_STRIDE 132   // floats; 528B row, 16B aligned for cp.async

// Scratch
__device__ float  g_tsf[NN * DD];          // self_feats @ self_weights
__device__ float2 g_wpack[16 * 16 * 32];   // link_weights in mma-B-fragment order (tf32)

__device__ __forceinline__ uint32_t f2tf32(float x) {
    uint32_t r;
    asm("cvt.rna.tf32.f32 %0, %1;" : "=r"(r) : "f"(x));
    return r;
}

__device__ __forceinline__ float sigf(float x) {
    return __fdividef(1.0f, 1.0f + __expf(-x));
}

__device__ __forceinline__ void mma_tf32(float* c, const uint32_t* a, uint32_t b0, uint32_t b1) {
    asm volatile(
        "mma.sync.aligned.m16n8k8.row.col.f32.tf32.tf32.f32 "
        "{%0,%1,%2,%3}, {%4,%5,%6,%7}, {%8,%9}, {%0,%1,%2,%3};\n"
        : "+f"(c[0]), "+f"(c[1]), "+f"(c[2]), "+f"(c[3])
        : "r"(a[0]), "r"(a[1]), "r"(a[2]), "r"(a[3]), "r"(b0), "r"(b1));
}

__device__ __forceinline__ void cp_async16(float* smem_dst, const float* gsrc) {
    uint32_t s = (uint32_t)__cvta_generic_to_shared(smem_dst);
    asm volatile("cp.async.cg.shared.global [%0], [%1], 16;\n" :: "r"(s), "l"(gsrc));
}

// ---------------------------------------------------------------------------
// Setup 1: pack link_weights into per-fragment lane order (tf32).
// ---------------------------------------------------------------------------
__global__ __launch_bounds__(256) void pack_w_kernel(const float* __restrict__ lW)
{
    int i = blockIdx.x * 256 + threadIdx.x;     // 0 .. 8191
    int ks = i >> 9;
    int rem = i & 511;
    int ct = rem >> 5;
    int lane = rem & 31;
    int g = lane >> 2, tg = lane & 3;
    float2 v;
    v.x = __uint_as_float(f2tf32(lW[(ks * 8 + tg) * 128 + ct * 8 + g]));
    v.y = __uint_as_float(f2tf32(lW[(ks * 8 + 4 + tg) * 128 + ct * 8 + g]));
    g_wpack[i] = v;
}

// ---------------------------------------------------------------------------
// Setup 2: g_tsf = self_feats @ self_weights. 32 nodes/CTA, 256 thr, fp32.
// ---------------------------------------------------------------------------
#define PRO_BS 132
#define PRO_AS 36

__global__ __launch_bounds__(256, 2) void tsf_gemm_kernel(
    const float* __restrict__ sf, const float* __restrict__ W)
{
    extern __shared__ float sm[];
    float* sB = sm;                  // [128][132]
    float* sA = sm + 128 * PRO_BS;   // [128][36]

    int tid = threadIdx.x;
    int nb = blockIdx.x * 32;

    for (int i = tid; i < 4096; i += 256) {
        int d = i >> 5, c = (i & 31) * 4;
        float4 v = *(const float4*)(W + d * 128 + c);
        *(float4*)(sB + d * PRO_BS + c) = v;
    }
    for (int i = tid; i < 4096; i += 256) {
        int m = i >> 7, d = i & 127;
        sA[d * PRO_AS + m] = sf[(nb + m) * 128 + d];
    }
    __syncthreads();

    int tr = tid >> 5, lane = tid & 31;
    int m0 = tr * 4, e0 = lane * 4;
    float acc[4][4] = {};

#pragma unroll 4
    for (int d = 0; d < 128; ++d) {
        float4 b = *(float4*)(sB + d * PRO_BS + e0);
        float4 a = *(float4*)(sA + d * PRO_AS + m0);
        float av[4] = {a.x, a.y, a.z, a.w};
        float bv[4] = {b.x, b.y, b.z, b.w};
#pragma unroll
        for (int i = 0; i < 4; ++i)
#pragma unroll
            for (int j = 0; j < 4; ++j)
                acc[i][j] += av[i] * bv[j];
    }
#pragma unroll
    for (int i = 0; i < 4; ++i) {
        float4 o = make_float4(acc[i][0], acc[i][1], acc[i][2], acc[i][3]);
        *(float4*)(g_tsf + (size_t)(nb + m0 + i) * 128 + e0) = o;
    }
}

// ---------------------------------------------------------------------------
// Main fused kernel. 2 nodes (64 rows) per CTA, 256 threads, 4 CTAs/SM.
//  - A (link tile) via cp.async -> smem (fp32, tf32-truncated in mma)
//  - B from g_wpack: one coalesced LDG.64 per fragment (L2-hot)
//  - gate: coalesced LDG.128 row reads + warp reduce (8 rows/warp)
//  - GEMM: warp = 32 rows x 32 cols, m16n8k8 tf32
//  - P = sigmoid(acc)*gate/(32p) into dead A-tile smem
//  - reduce: coalesced neigh * P, * g_tsf, relu, store
// ---------------------------------------------------------------------------
__global__ __launch_bounds__(256, 4) void rwagg_fused_kernel(
    const float* __restrict__ self_vecs, const float* __restrict__ neigh,
    const float* __restrict__ link, const float* __restrict__ probs,
    const float* __restrict__ gsw, const float* __restrict__ gnw,
    const float* __restrict__ glw, float* __restrict__ out)
{
    extern __shared__ float sm[];
    float* As       = sm;                       // [64][132] link tile -> later P
    float* s_gnw    = As + 64 * AS_STRIDE;      // 128
    float* s_glw    = s_gnw + 128;              // 128
    float* s_gscale = s_glw + 128;              // 64
    float* s_tself  = s_gscale + 64;            // 4 (2 used)
    float* s_outb   = s_tself + 4;              // 256

    int tid = threadIdx.x, lane = tid & 31, wid = tid >> 5;
    int g = lane >> 2, tg = lane & 3;
    int node2 = blockIdx.x * 2;
    int row_base = blockIdx.x * 64;

    // ---- stage 0: cp.async the A (link) tile -----------------------------
    for (int i = tid; i < 2048; i += 256) {
        int r = i >> 5, c = (i & 31) * 4;
        cp_async16(As + r * AS_STRIDE + c,
                   link + (size_t)(row_base + r) * 128 + c);
    }
    asm volatile("cp.async.commit_group;\n");

    // in the shadow: gate weight vectors + tself dots
    if (tid < 128) s_gnw[tid] = __ldg(gnw + tid);
    else           s_glw[tid - 128] = __ldg(glw + tid - 128);

    if (wid < 2) {
        float4 sv = __ldg((const float4*)(self_vecs + (size_t)(node2 + wid) * 128 + lane * 4));
        float4 gw = __ldg((const float4*)(gsw + lane * 4));
        float p = sv.x * gw.x + sv.y * gw.y + sv.z * gw.z + sv.w * gw.w;
#pragma unroll
        for (int off = 16; off; off >>= 1) p += __shfl_xor_sync(FULLMASK, p, off);
        if (lane == 0) s_tself[wid] = p;
    }

    asm volatile("cp.async.wait_group 0;\n" ::: "memory");
    __syncthreads();

    // ---- gate: warp w handles rows w*8 .. w*8+7, fully coalesced ---------
    {
        int rb = wid * 8;
#pragma unroll
        for (int j = 0; j < 8; ++j) {
            int m = rb + j;
            float4 n4 = __ldg((const float4*)(neigh + (size_t)(row_base + m) * 128 + lane * 4));
            float4 l4 = *(const float4*)(As + m * AS_STRIDE + lane * 4);
            float4 gw = *(const float4*)(s_gnw + lane * 4);
            float4 lw = *(const float4*)(s_glw + lane * 4);
            float dot = n4.x * gw.x + n4.y * gw.y + n4.z * gw.z + n4.w * gw.w
                      + l4.x * lw.x + l4.y * lw.y + l4.z * lw.z + l4.w * lw.w;
#pragma unroll
            for (int off = 16; off; off >>= 1) dot += __shfl_xor_sync(FULLMASK, dot, off);
            if (lane == 0) {
                float logit = s_tself[m >> 5] + dot;
                s_gscale[m] = sigf(logit) * __fdividef(1.0f, 32.0f * __ldg(probs + row_base + m));
            }
        }
    }
    __syncthreads();

    // ---- GEMM: warp (wr, wc) -> rows wr*32..+31, cols wc*32..+31 ---------
    int wr = wid & 1, wc = wid >> 1;
    float acc[2][4][4];
#pragma unroll
    for (int mt = 0; mt < 2; ++mt)
#pragma unroll
        for (int nt = 0; nt < 4; ++nt)
#pragma unroll
            for (int q = 0; q < 4; ++q) acc[mt][nt][q] = 0.0f;

    const float2* wp = g_wpack + (size_t)(wc * 4) * 32 + lane;
#pragma unroll
    for (int ks = 0; ks < 16; ++ks) {
        int k0 = ks * 8;
        float2 bf[4];
#pragma unroll
        for (int nt = 0; nt < 4; ++nt)
            bf[nt] = __ldg(wp + ks * 512 + nt * 32);
#pragma unroll
        for (int mt = 0; mt < 2; ++mt) {
            const float* ap = As + (wr * 32 + mt * 16) * AS_STRIDE + k0;
            uint32_t a[4];
            a[0] = __float_as_uint(ap[g * AS_STRIDE + tg]);
            a[1] = __float_as_uint(ap[(8 + g) * AS_STRIDE + tg]);
            a[2] = __float_as_uint(ap[g * AS_STRIDE + 4 + tg]);
            a[3] = __float_as_uint(ap[(8 + g) * AS_STRIDE + 4 + tg]);
#pragma unroll
            for (int nt = 0; nt < 4; ++nt)
                mma_tf32(acc[mt][nt], a,
                         __float_as_uint(bf[nt].x), __float_as_uint(bf[nt].y));
        }
    }

    // all warps done reading A fragments before P overwrites the tile
    __syncthreads();

    // ---- P = sigmoid(acc) * gscale -> reuse As ---------------------------
#pragma unroll
    for (int mt = 0; mt < 2; ++mt) {
        int r1 = wr * 32 + mt * 16 + g;
        int r2 = r1 + 8;
        float gs1 = s_gscale[r1];
        float gs2 = s_gscale[r2];
#pragma unroll
        for (int nt = 0; nt < 4; ++nt) {
            int c = wc * 32 + nt * 8 + tg * 2;
            float2 p1, p2;
            p1.x = sigf(acc[mt][nt][0]) * gs1;
            p1.y = sigf(acc[mt][nt][1]) * gs1;
            p2.x = sigf(acc[mt][nt][2]) * gs2;
            p2.y = sigf(acc[mt][nt][3]) * gs2;
            *(float2*)(As + r1 * AS_STRIDE + c) = p1;
            *(float2*)(As + r2 * AS_STRIDE + c) = p2;
        }
    }
    __syncthreads();

    // ---- reduce: coalesced neigh * P, sum over k -------------------------
    {
        int e = tid & 127, h = tid >> 7;
        float accn[2];
#pragma unroll
        for (int n = 0; n < 2; ++n) {
            float s = 0.0f;
            int m0 = n * 32 + h * 16;
#pragma unroll
            for (int k = 0; k < 16; ++k) {
                int m = m0 + k;
                s = fmaf(__ldg(neigh + (size_t)(row_base + m) * 128 + e),
                         As[m * AS_STRIDE + e], s);
            }
            accn[n] = s;
        }
        if (h == 1) {
#pragma unroll
            for (int n = 0; n < 2; ++n) s_outb[n * 128 + e] = accn[n];
        }
        __syncthreads();
        if (h == 0) {
#pragma unroll
            for (int n = 0; n < 2; ++n) {
                float v = (accn[n] + s_outb[n * 128 + e])
                        * g_tsf[(size_t)(node2 + n) * 128 + e];
                out[(size_t)(node2 + n) * 128 + e] = fmaxf(v, 0.0f);
            }
        }
    }
}

// ---------------------------------------------------------------------------
extern "C" void kernel_launch(void* const* d_in, const int* in_sizes, int n_in,
                              void* d_out, int out_size)
{
    const float* self_feats = (const float*)d_in[0];
    const float* self_vecs  = (const float*)d_in[1];
    const float* neigh      = (const float*)d_in[2];
    const float* link       = (const float*)d_in[3];
    const float* probs      = (const float*)d_in[4];
    const float* gsw        = (const float*)d_in[5];
    const float* gnw        = (const float*)d_in[6];
    const float* glw        = (const float*)d_in[7];
    const float* sW         = (const float*)d_in[8];
    const float* lW         = (const float*)d_in[9];
    float* out = (float*)d_out;

    const int pro_smem  = (128 * PRO_BS + 128 * PRO_AS) * 4;             // 86016 B
    const int main_smem = (64 * AS_STRIDE + 2 * 128 + 64 + 4 + 256) * 4; // 36112 B

    cudaFuncSetAttribute(tsf_gemm_kernel,
                         cudaFuncAttributeMaxDynamicSharedMemorySize, pro_smem);
    cudaFuncSetAttribute(rwagg_fused_kernel,
                         cudaFuncAttributeMaxDynamicSharedMemorySize, main_smem);

    pack_w_kernel<<<32, 256>>>(lW);
    tsf_gemm_kernel<<<NN / 32, 256, pro_smem>>>(self_feats, sW);
    rwagg_fused_kernel<<<NN / 2, 256, main_smem>>>(
        self_vecs, neigh, link, probs, gsw, gnw, glw, out);
}

// round 11
// speedup vs baseline: 1.6517x; 1.0044x over previous
#include <cuda_runtime.h>
#include <cstdint>

// Problem constants
#define NN 20000
#define KK 32
#define DD 128

#define FULLMASK 0xffffffffu
#define AS_STRIDE 132   // floats; 528B row, 16B aligned for cp.async
#define AS_ROWS   66    // 64 link rows + 2 self_feats rows

// Scratch: weights packed in mma-B-fragment lane order (tf32)
__device__ float2 g_wpackL[16 * 16 * 32];   // link_weights
__device__ float2 g_wpackS[16 * 16 * 32];   // self_weights

__device__ __forceinline__ uint32_t f2tf32(float x) {
    uint32_t r;
    asm("cvt.rna.tf32.f32 %0, %1;" : "=r"(r) : "f"(x));
    return r;
}

__device__ __forceinline__ float sigf(float x) {
    return __fdividef(1.0f, 1.0f + __expf(-x));
}

__device__ __forceinline__ void mma_tf32(float* c, const uint32_t* a, uint32_t b0, uint32_t b1) {
    asm volatile(
        "mma.sync.aligned.m16n8k8.row.col.f32.tf32.tf32.f32 "
        "{%0,%1,%2,%3}, {%4,%5,%6,%7}, {%8,%9}, {%0,%1,%2,%3};\n"
        : "+f"(c[0]), "+f"(c[1]), "+f"(c[2]), "+f"(c[3])
        : "r"(a[0]), "r"(a[1]), "r"(a[2]), "r"(a[3]), "r"(b0), "r"(b1));
}

__device__ __forceinline__ void cp_async16(float* smem_dst, const float* gsrc) {
    uint32_t s = (uint32_t)__cvta_generic_to_shared(smem_dst);
    asm volatile("cp.async.cg.shared.global [%0], [%1], 16;\n" :: "r"(s), "l"(gsrc));
}

// ---------------------------------------------------------------------------
// Setup: pack link_weights (blocks 0..31) and self_weights (blocks 32..63)
// into per-fragment lane order, tf32-rounded.
// Fragment (ks, ct): lane (g=l>>2, tg=l&3) holds
//   b0 = W[ks*8 + tg][ct*8 + g],  b1 = W[ks*8 + 4 + tg][ct*8 + g]
// ---------------------------------------------------------------------------
__global__ __launch_bounds__(256) void pack_w_kernel(
    const float* __restrict__ lW, const float* __restrict__ sW)
{
    int b = blockIdx.x;
    const float* W = (b < 32) ? lW : sW;
    float2* dst = (b < 32) ? g_wpackL : g_wpackS;
    int i = (b & 31) * 256 + threadIdx.x;        // 0 .. 8191
    int ks = i >> 9;
    int rem = i & 511;
    int ct = rem >> 5;
    int lane = rem & 31;
    int g = lane >> 2, tg = lane & 3;
    float2 v;
    v.x = __uint_as_float(f2tf32(W[(ks * 8 + tg) * 128 + ct * 8 + g]));
    v.y = __uint_as_float(f2tf32(W[(ks * 8 + 4 + tg) * 128 + ct * 8 + g]));
    dst[i] = v;
}

// ---------------------------------------------------------------------------
// Main fused kernel. 2 nodes (64 rows) per CTA, 256 threads, 4 CTAs/SM.
//  - A tile: 64 link rows + 2 self_feats rows via cp.async
//  - gate computed from GLOBAL neigh/link while the cp.async is in flight
//    (tself dot folded into the same lane-reduction)
//  - GEMM: warp = 32 rows x 32 cols tf32 mma vs packed lW; plus a shared
//    extra 16-row fragment (self_feats rows 64/65) vs packed sW -> tsf
//  - P = sigmoid(acc)*gate/(32p) into dead A-tile smem
//  - reduce: float2 coalesced neigh * P, * tsf, relu, float2 store
// ---------------------------------------------------------------------------
__global__ __launch_bounds__(256, 4) void rwagg_fused_kernel(
    const float* __restrict__ self_feats,
    const float* __restrict__ self_vecs, const float* __restrict__ neigh,
    const float* __restrict__ link, const float* __restrict__ probs,
    const float* __restrict__ gsw, const float* __restrict__ gnw,
    const float* __restrict__ glw, float* __restrict__ out)
{
    extern __shared__ float sm[];
    float* As       = sm;                        // [66][132]; rows 0-63 link -> P
    float* s_gscale = As + AS_ROWS * AS_STRIDE;  // 64
    float* s_tsf    = s_gscale + 64;             // 2 x 128
    float* s_outb   = s_tsf + 256;               // 256

    int tid = threadIdx.x, lane = tid & 31, wid = tid >> 5;
    int g = lane >> 2, tg = lane & 3;
    int node2 = blockIdx.x * 2;
    int row_base = blockIdx.x * 64;

    // ---- stage 0: cp.async A tile (64 link rows + 2 self_feats rows) ----
    for (int i = tid; i < 2048; i += 256) {
        int r = i >> 5, c = (i & 31) * 4;
        cp_async16(As + r * AS_STRIDE + c,
                   link + (size_t)(row_base + r) * 128 + c);
    }
    if (tid < 64) {
        int r = tid >> 5, c = (tid & 31) * 4;
        cp_async16(As + (64 + r) * AS_STRIDE + c,
                   self_feats + (size_t)(node2 + r) * 128 + c);
    }
    asm volatile("cp.async.commit_group;\n");

    // ---- gate UNDER the cp.async: global neigh+link reads ----------------
    {
        int node = wid >> 2;                     // warp's node (rows wid*8..+7)
        float4 gw = __ldg((const float4*)(gnw + lane * 4));
        float4 lw = __ldg((const float4*)(glw + lane * 4));
        float4 sv = __ldg((const float4*)(self_vecs + (size_t)(node2 + node) * 128 + lane * 4));
        float4 gs4 = __ldg((const float4*)(gsw + lane * 4));
        float tpart = sv.x * gs4.x + sv.y * gs4.y + sv.z * gs4.z + sv.w * gs4.w;
        int rb = wid * 8;
#pragma unroll
        for (int j = 0; j < 8; ++j) {
            int m = rb + j;
            float4 n4 = __ldg((const float4*)(neigh + (size_t)(row_base + m) * 128 + lane * 4));
            float4 l4 = __ldg((const float4*)(link + (size_t)(row_base + m) * 128 + lane * 4));
            float dot = tpart
                      + n4.x * gw.x + n4.y * gw.y + n4.z * gw.z + n4.w * gw.w
                      + l4.x * lw.x + l4.y * lw.y + l4.z * lw.z + l4.w * lw.w;
#pragma unroll
            for (int off = 16; off; off >>= 1) dot += __shfl_xor_sync(FULLMASK, dot, off);
            if (lane == 0)
                s_gscale[m] = sigf(dot) * __fdividef(1.0f, 32.0f * __ldg(probs + row_base + m));
        }
    }

    asm volatile("cp.async.wait_group 0;\n" ::: "memory");
    __syncthreads();

    // ---- GEMM: warp (wr, wc) -> rows wr*32..+31, cols wc*32..+31 ---------
    int wr = wid & 1, wc = wid >> 1;
    float acc[2][4][4];
    float acce[2][4];        // extra fragment (tsf): 2 nt per warp, split by wr
#pragma unroll
    for (int mt = 0; mt < 2; ++mt)
#pragma unroll
        for (int nt = 0; nt < 4; ++nt)
#pragma unroll
            for (int q = 0; q < 4; ++q) acc[mt][nt][q] = 0.0f;
#pragma unroll
    for (int j = 0; j < 2; ++j)
#pragma unroll
        for (int q = 0; q < 4; ++q) acce[j][q] = 0.0f;

    const float2* wpL = g_wpackL + (size_t)(wc * 4) * 32 + lane;
    const float2* wpS = g_wpackS + (size_t)(wc * 4 + wr * 2) * 32 + lane;
#pragma unroll
    for (int ks = 0; ks < 16; ++ks) {
        int k0 = ks * 8;
        float2 bf[4];
#pragma unroll
        for (int nt = 0; nt < 4; ++nt)
            bf[nt] = __ldg(wpL + ks * 512 + nt * 32);
#pragma unroll
        for (int mt = 0; mt < 2; ++mt) {
            const float* ap = As + (wr * 32 + mt * 16) * AS_STRIDE + k0;
            uint32_t a[4];
            a[0] = __float_as_uint(ap[g * AS_STRIDE + tg]);
            a[1] = __float_as_uint(ap[(8 + g) * AS_STRIDE + tg]);
            a[2] = __float_as_uint(ap[g * AS_STRIDE + 4 + tg]);
            a[3] = __float_as_uint(ap[(8 + g) * AS_STRIDE + 4 + tg]);
#pragma unroll
            for (int nt = 0; nt < 4; ++nt)
                mma_tf32(acc[mt][nt], a,
                         __float_as_uint(bf[nt].x), __float_as_uint(bf[nt].y));
        }
        // extra fragment: row 64 = node0 sf, row 65 = node1 sf (rows 66..79
        // of the logical 16-row fragment read garbage but are discarded)
        {
            // clamp fragment row reads into the allocated 66 rows:
            // rows used: 64+g (g=0..7) and 72+g -> fold to 64 + (g&1) pattern
            // Instead read the 16-row fragment from row 64 with stride 0 for
            // out-of-range rows replaced by row 64/65 duplicates -- values in
            // rows >=66 are never used (only g<2 results are stored), but the
            // LDS must stay in bounds, so map row index r>=2 to r&1.
            int r0 = g & 1;          // in-bounds substitute rows
            int r1 = g & 1;
            uint32_t a[4];
            a[0] = __float_as_uint(As[(64 + ((g < 2) ? g : r0)) * AS_STRIDE + k0 + tg]);
            a[1] = __float_as_uint(As[(64 + r1) * AS_STRIDE + k0 + tg]);
            a[2] = __float_as_uint(As[(64 + ((g < 2) ? g : r0)) * AS_STRIDE + k0 + 4 + tg]);
            a[3] = __float_as_uint(As[(64 + r1) * AS_STRIDE + k0 + 4 + tg]);
#pragma unroll
            for (int j = 0; j < 2; ++j) {
                float2 be = __ldg(wpS + ks * 512 + j * 32);
                mma_tf32(acce[j], a,
                         __float_as_uint(be.x), __float_as_uint(be.y));
            }
        }
    }

    __syncthreads();   // A-frag reads done before P overwrites the tile

    // ---- P = sigmoid(acc) * gscale -> reuse As rows 0..63 ----------------
#pragma unroll
    for (int mt = 0; mt < 2; ++mt) {
        int r1 = wr * 32 + mt * 16 + g;
        int r2 = r1 + 8;
        float gs1 = s_gscale[r1];
        float gs2 = s_gscale[r2];
#pragma unroll
        for (int nt = 0; nt < 4; ++nt) {
            int c = wc * 32 + nt * 8 + tg * 2;
            float2 p1, p2;
            p1.x = sigf(acc[mt][nt][0]) * gs1;
            p1.y = sigf(acc[mt][nt][1]) * gs1;
            p2.x = sigf(acc[mt][nt][2]) * gs2;
            p2.y = sigf(acc[mt][nt][3]) * gs2;
            *(float2*)(As + r1 * AS_STRIDE + c) = p1;
            *(float2*)(As + r2 * AS_STRIDE + c) = p2;
        }
    }
    // tsf store: fragment row (64 + g) holds node g's tsf; only g<2 valid.
    // c registers {0,1} cover fragment rows g (upper half {2,3} -> rows 8+g,
    // invalid). Each warp covers nt = wr*2 + j, so all 16 float2 columns of
    // both nodes get written across the 8 warps.
    if (g < 2) {
#pragma unroll
        for (int j = 0; j < 2; ++j) {
            int nt = wr * 2 + j;
            int c = wc * 32 + nt * 8 + tg * 2;
            float2 t;
            t.x = acce[j][0];
            t.y = acce[j][1];
            *(float2*)(s_tsf + g * 128 + c) = t;
        }
    }
    __syncthreads();

    // ---- reduce: float2 coalesced neigh * P, sum over k ------------------
    {
        int c2 = tid & 63;                 // float2 column
        int n  = (tid >> 6) & 1;           // node within CTA
        int h  = tid >> 7;                 // k-half
        int e  = c2 * 2;
        float2 s = make_float2(0.0f, 0.0f);
        int m0 = n * 32 + h * 16;
#pragma unroll
        for (int k = 0; k < 16; ++k) {
            int m = m0 + k;
            float2 nv = __ldg((const float2*)(neigh + (size_t)(row_base + m) * 128 + e));
            float2 pv = *(const float2*)(As + m * AS_STRIDE + e);
            s.x = fmaf(nv.x, pv.x, s.x);
            s.y = fmaf(nv.y, pv.y, s.y);
        }
        if (h == 1) *(float2*)(s_outb + n * 128 + e) = s;
        __syncthreads();
        if (h == 0) {
            float2 o = *(const float2*)(s_outb + n * 128 + e);
            float2 t = *(const float2*)(s_tsf + n * 128 + e);
            float2 v;
            v.x = fmaxf((s.x + o.x) * t.x, 0.0f);
            v.y = fmaxf((s.y + o.y) * t.y, 0.0f);
            *(float2*)(out + (size_t)(node2 + n) * 128 + e) = v;
        }
    }
}

// ---------------------------------------------------------------------------
extern "C" void kernel_launch(void* const* d_in, const int* in_sizes, int n_in,
                              void* d_out, int out_size)
{
    const float* self_feats = (const float*)d_in[0];
    const float* self_vecs  = (const float*)d_in[1];
    const float* neigh      = (const float*)d_in[2];
    const float* link       = (const float*)d_in[3];
    const float* probs      = (const float*)d_in[4];
    const float* gsw        = (const float*)d_in[5];
    const float* gnw        = (const float*)d_in[6];
    const float* glw        = (const float*)d_in[7];
    const float* sW         = (const float*)d_in[8];
    const float* lW         = (const float*)d_in[9];
    float* out = (float*)d_out;

    const int main_smem = (AS_ROWS * AS_STRIDE + 64 + 256 + 256) * 4;  // 37152 B

    cudaFuncSetAttribute(rwagg_fused_kernel,
                         cudaFuncAttributeMaxDynamicSharedMemorySize, main_smem);

    pack_w_kernel<<<64, 256>>>(lW, sW);
    rwagg_fused_kernel<<<NN / 2, 256, main_smem>>>(
        self_feats, self_vecs, neigh, link, probs, gsw, gnw, glw, out);
}

// round 13
// speedup vs baseline: 1.7299x; 1.0473x over previous
#include <cuda_runtime.h>
#include <cstdint>

// Problem constants
#define NN 20000
#define KK 32
#define DD 128

#define FULLMASK 0xffffffffu
#define AS_STRIDE 132   // floats; 528B row, 16B aligned for cp.async
#define AS_ROWS   66    // 64 link rows + 2 self_feats rows

// Scratch: weights packed in mma-B-fragment lane order (tf32)
__device__ float2 g_wpackL[16 * 16 * 32];   // link_weights
__device__ float2 g_wpackS[16 * 16 * 32];   // self_weights

__device__ __forceinline__ uint32_t f2tf32(float x) {
    uint32_t r;
    asm("cvt.rna.tf32.f32 %0, %1;" : "=r"(r) : "f"(x));
    return r;
}

__device__ __forceinline__ float sigf(float x) {
    return __fdividef(1.0f, 1.0f + __expf(-x));
}

__device__ __forceinline__ void mma_tf32(float* c, const uint32_t* a, uint32_t b0, uint32_t b1) {
    asm volatile(
        "mma.sync.aligned.m16n8k8.row.col.f32.tf32.tf32.f32 "
        "{%0,%1,%2,%3}, {%4,%5,%6,%7}, {%8,%9}, {%0,%1,%2,%3};\n"
        : "+f"(c[0]), "+f"(c[1]), "+f"(c[2]), "+f"(c[3])
        : "r"(a[0]), "r"(a[1]), "r"(a[2]), "r"(a[3]), "r"(b0), "r"(b1));
}

__device__ __forceinline__ void cp_async16(float* smem_dst, const float* gsrc) {
    uint32_t s = (uint32_t)__cvta_generic_to_shared(smem_dst);
    asm volatile("cp.async.cg.shared.global [%0], [%1], 16;\n" :: "r"(s), "l"(gsrc));
}

// ---------------------------------------------------------------------------
// Setup: pack link_weights (blocks 0..31) and self_weights (blocks 32..63)
// into per-fragment lane order, tf32-rounded.
// Fragment (ks, ct): lane (g=l>>2, tg=l&3) holds
//   b0 = W[ks*8 + tg][ct*8 + g],  b1 = W[ks*8 + 4 + tg][ct*8 + g]
// ---------------------------------------------------------------------------
__global__ __launch_bounds__(256) void pack_w_kernel(
    const float* __restrict__ lW, const float* __restrict__ sW)
{
    int b = blockIdx.x;
    const float* W = (b < 32) ? lW : sW;
    float2* dst = (b < 32) ? g_wpackL : g_wpackS;
    int i = (b & 31) * 256 + threadIdx.x;        // 0 .. 8191
    int ks = i >> 9;
    int rem = i & 511;
    int ct = rem >> 5;
    int lane = rem & 31;
    int g = lane >> 2, tg = lane & 3;
    float2 v;
    v.x = __uint_as_float(f2tf32(W[(ks * 8 + tg) * 128 + ct * 8 + g]));
    v.y = __uint_as_float(f2tf32(W[(ks * 8 + 4 + tg) * 128 + ct * 8 + g]));
    dst[i] = v;
}

// ---------------------------------------------------------------------------
// Main fused kernel. 2 nodes (64 rows) per CTA, 256 threads, 4 CTAs/SM.
//  - A tile: 64 link rows + 2 self_feats rows via cp.async
//  - gate part A (neigh dot + tself, probs) UNDER the DMA, from global
//  - gate part B (link dot) post-wait, from the SMEM tile -> s_gscale
//  - GEMM: warp = 32 rows x 32 cols tf32 mma vs packed lW; plus a shared
//    extra 16-row fragment (self_feats rows 64/65) vs packed sW -> tsf
//  - P = sigmoid(acc)*gscale into dead A-tile smem
//  - reduce: one thread per (node, column), 32 k-rows, * tsf, relu, store
// ---------------------------------------------------------------------------
__global__ __launch_bounds__(256, 4) void rwagg_fused_kernel(
    const float* __restrict__ self_feats,
    const float* __restrict__ self_vecs, const float* __restrict__ neigh,
    const float* __restrict__ link, const float* __restrict__ probs,
    const float* __restrict__ gsw, const float* __restrict__ gnw,
    const float* __restrict__ glw, float* __restrict__ out)
{
    extern __shared__ float sm[];
    float* As       = sm;                        // [66][132]; rows 0-63 link -> P
    float* s_gpart  = As + AS_ROWS * AS_STRIDE;  // 64: tself + neigh.gnw
    float* s_invp   = s_gpart + 64;              // 64: 1/(32 p)
    float* s_gscale = s_invp + 64;               // 64
    float* s_tsf    = s_gscale + 64;             // 2 x 128

    int tid = threadIdx.x, lane = tid & 31, wid = tid >> 5;
    int g = lane >> 2, tg = lane & 3;
    int node2 = blockIdx.x * 2;
    int row_base = blockIdx.x * 64;

    // ---- stage 0: cp.async A tile (64 link rows + 2 self_feats rows) ----
    for (int i = tid; i < 2048; i += 256) {
        int r = i >> 5, c = (i & 31) * 4;
        cp_async16(As + r * AS_STRIDE + c,
                   link + (size_t)(row_base + r) * 128 + c);
    }
    if (tid < 64) {
        int r = tid >> 5, c = (tid & 31) * 4;
        cp_async16(As + (64 + r) * AS_STRIDE + c,
                   self_feats + (size_t)(node2 + r) * 128 + c);
    }
    asm volatile("cp.async.commit_group;\n");

    // ---- gate part A UNDER the DMA: tself + neigh.gnw, 1/(32p) -----------
    int rb = wid * 8;
    {
        int node = wid >> 2;                     // warp's node (rows wid*8..+7)
        float4 gw = __ldg((const float4*)(gnw + lane * 4));
        float4 sv = __ldg((const float4*)(self_vecs + (size_t)(node2 + node) * 128 + lane * 4));
        float4 gs4 = __ldg((const float4*)(gsw + lane * 4));
        float tpart = sv.x * gs4.x + sv.y * gs4.y + sv.z * gs4.z + sv.w * gs4.w;
#pragma unroll
        for (int j = 0; j < 8; ++j) {
            int m = rb + j;
            float4 n4 = __ldg((const float4*)(neigh + (size_t)(row_base + m) * 128 + lane * 4));
            float dot = tpart
                      + n4.x * gw.x + n4.y * gw.y + n4.z * gw.z + n4.w * gw.w;
#pragma unroll
            for (int off = 16; off; off >>= 1) dot += __shfl_xor_sync(FULLMASK, dot, off);
            if (lane == 0) {
                s_gpart[m] = dot;
                s_invp[m]  = __fdividef(1.0f, 32.0f * __ldg(probs + row_base + m));
            }
        }
    }

    asm volatile("cp.async.wait_group 0;\n" ::: "memory");
    __syncthreads();

    // ---- gate part B from SMEM: link.glw; finish gscale ------------------
    {
        float4 lw = __ldg((const float4*)(glw + lane * 4));
#pragma unroll
        for (int j = 0; j < 8; ++j) {
            int m = rb + j;
            float4 l4 = *(const float4*)(As + m * AS_STRIDE + lane * 4);
            float dot = l4.x * lw.x + l4.y * lw.y + l4.z * lw.z + l4.w * lw.w;
#pragma unroll
            for (int off = 16; off; off >>= 1) dot += __shfl_xor_sync(FULLMASK, dot, off);
            if (lane == 0)
                s_gscale[m] = sigf(s_gpart[m] + dot) * s_invp[m];
        }
    }
    // no barrier needed before GEMM: GEMM reads only As (ready); s_gscale is
    // ordered before its P-phase readers by the post-GEMM __syncthreads.

    // ---- GEMM: warp (wr, wc) -> rows wr*32..+31, cols wc*32..+31 ---------
    int wr = wid & 1, wc = wid >> 1;
    float acc[2][4][4];
    float acce[2][4];        // extra fragment (tsf): 2 nt per warp, split by wr
#pragma unroll
    for (int mt = 0; mt < 2; ++mt)
#pragma unroll
        for (int nt = 0; nt < 4; ++nt)
#pragma unroll
            for (int q = 0; q < 4; ++q) acc[mt][nt][q] = 0.0f;
#pragma unroll
    for (int j = 0; j < 2; ++j)
#pragma unroll
        for (int q = 0; q < 4; ++q) acce[j][q] = 0.0f;

    const float2* wpL = g_wpackL + (size_t)(wc * 4) * 32 + lane;
    const float2* wpS = g_wpackS + (size_t)(wc * 4 + wr * 2) * 32 + lane;
#pragma unroll
    for (int ks = 0; ks < 16; ++ks) {
        int k0 = ks * 8;
        float2 bf[4];
#pragma unroll
        for (int nt = 0; nt < 4; ++nt)
            bf[nt] = __ldg(wpL + ks * 512 + nt * 32);
#pragma unroll
        for (int mt = 0; mt < 2; ++mt) {
            const float* ap = As + (wr * 32 + mt * 16) * AS_STRIDE + k0;
            uint32_t a[4];
            a[0] = __float_as_uint(ap[g * AS_STRIDE + tg]);
            a[1] = __float_as_uint(ap[(8 + g) * AS_STRIDE + tg]);
            a[2] = __float_as_uint(ap[g * AS_STRIDE + 4 + tg]);
            a[3] = __float_as_uint(ap[(8 + g) * AS_STRIDE + 4 + tg]);
#pragma unroll
            for (int nt = 0; nt < 4; ++nt)
                mma_tf32(acc[mt][nt], a,
                         __float_as_uint(bf[nt].x), __float_as_uint(bf[nt].y));
        }
        // extra fragment: row 64 = node0 sf, row 65 = node1 sf; out-of-range
        // fragment rows are clamped in-bounds (their results are discarded)
        {
            int rsub = g & 1;
            uint32_t a[4];
            a[0] = __float_as_uint(As[(64 + ((g < 2) ? g : rsub)) * AS_STRIDE + k0 + tg]);
            a[1] = __float_as_uint(As[(64 + rsub) * AS_STRIDE + k0 + tg]);
            a[2] = __float_as_uint(As[(64 + ((g < 2) ? g : rsub)) * AS_STRIDE + k0 + 4 + tg]);
            a[3] = __float_as_uint(As[(64 + rsub) * AS_STRIDE + k0 + 4 + tg]);
#pragma unroll
            for (int j = 0; j < 2; ++j) {
                float2 be = __ldg(wpS + ks * 512 + j * 32);
                mma_tf32(acce[j], a,
                         __float_as_uint(be.x), __float_as_uint(be.y));
            }
        }
    }

    __syncthreads();   // A-frag reads done before P overwrites; s_gscale visible

    // ---- P = sigmoid(acc) * gscale -> reuse As rows 0..63 ----------------
#pragma unroll
    for (int mt = 0; mt < 2; ++mt) {
        int r1 = wr * 32 + mt * 16 + g;
        int r2 = r1 + 8;
        float gs1 = s_gscale[r1];
        float gs2 = s_gscale[r2];
#pragma unroll
        for (int nt = 0; nt < 4; ++nt) {
            int c = wc * 32 + nt * 8 + tg * 2;
            float2 p1, p2;
            p1.x = sigf(acc[mt][nt][0]) * gs1;
            p1.y = sigf(acc[mt][nt][1]) * gs1;
            p2.x = sigf(acc[mt][nt][2]) * gs2;
            p2.y = sigf(acc[mt][nt][3]) * gs2;
            *(float2*)(As + r1 * AS_STRIDE + c) = p1;
            *(float2*)(As + r2 * AS_STRIDE + c) = p2;
        }
    }
    // tsf store: fragment row (64 + g) holds node g's tsf; only g<2 valid.
    if (g < 2) {
#pragma unroll
        for (int j = 0; j < 2; ++j) {
            int nt = wr * 2 + j;
            int c = wc * 32 + nt * 8 + tg * 2;
            float2 t;
            t.x = acce[j][0];
            t.y = acce[j][1];
            *(float2*)(s_tsf + g * 128 + c) = t;
        }
    }
    __syncthreads();

    // ---- reduce: one thread per (node, column), 32 k-rows ----------------
    {
        int e = tid & 127;
        int n = tid >> 7;
        const float* np = neigh + (size_t)(row_base + n * 32) * 128 + e;
        const float* pp = As + (n * 32) * AS_STRIDE + e;
        float s = 0.0f;
#pragma unroll
        for (int k = 0; k < 32; ++k)
            s = fmaf(__ldg(np + (size_t)k * 128), pp[k * AS_STRIDE], s);
        float v = s * s_tsf[n * 128 + e];
        out[(size_t)(node2 + n) * 128 + e] = fmaxf(v, 0.0f);
    }
}

// ---------------------------------------------------------------------------
extern "C" void kernel_launch(void* const* d_in, const int* in_sizes, int n_in,
                              void* d_out, int out_size)
{
    const float* self_feats = (const float*)d_in[0];
    const float* self_vecs  = (const float*)d_in[1];
    const float* neigh      = (const float*)d_in[2];
    const float* link       = (const float*)d_in[3];
    const float* probs      = (const float*)d_in[4];
    const float* gsw        = (const float*)d_in[5];
    const float* gnw        = (const float*)d_in[6];
    const float* glw        = (const float*)d_in[7];
    const float* sW         = (const float*)d_in[8];
    const float* lW         = (const float*)d_in[9];
    float* out = (float*)d_out;

    const int main_smem = (AS_ROWS * AS_STRIDE + 64 * 3 + 256) * 4;  // 36640 B

    cudaFuncSetAttribute(rwagg_fused_kernel,
                         cudaFuncAttributeMaxDynamicSharedMemorySize, main_smem);

    pack_w_kernel<<<64, 256>>>(lW, sW);
    rwagg_fused_kernel<<<NN / 2, 256, main_smem>>>(
        self_feats, self_vecs, neigh, link, probs, gsw, gnw, glw, out);
}